// round 1
// baseline (speedup 1.0000x reference)
#include <cuda_runtime.h>
#include <math.h>

#define Bb 8
#define Tt 256
#define Kk 20
#define Hh 768
#define Vv 30522
#define NSTEP 255            // T-1 LSTM steps
#define NTB (NSTEP*Bb)       // 2040 decoder tokens
#define TAUf 1.0f
#define ZBETA 1.0f

#define GTM 128
#define GTN 128
#define GBK 16
#define NVB ((Vv + GTN - 1) / GTN)   // 239 v-blocks

#define GL 128               // LSTM persistent blocks
#define NJ 6                 // hidden units per block (128*6 = 768)

// ---------------- device scratch (static, no allocations) ----------------
__device__ __align__(256) float d_trans[Kk*Kk];
__device__ __align__(256) float d_transexp[Kk*Kk];
__device__ __align__(256) float d_emission[Bb*Tt*Kk];     // [b][t][k]
__device__ __align__(256) float d_alphas[Tt*Bb*Kk];       // [t][b][k]
__device__ __align__(256) float d_relaxed[Tt*Bb*Kk];      // [t][b][k]
__device__ __align__(256) int   d_z[Tt*Bb];               // [t][b]
__device__ __align__(256) float d_decin[NSTEP*Bb*Hh];     // [t][b][h]
__device__ __align__(256) float d_hs[NSTEP*Bb*Hh];        // [t][b][h]
__device__ __align__(256) float d_hbuf[2*Bb*Hh];
__device__ __align__(256) float d_partial[2048*NVB];
__device__ __align__(256) float d_tgtlogit[NTB];
__device__ __align__(256) float d_entsum[2];              // ent_sum, mask_sum
__device__ volatile int d_flags[GL];

__device__ __forceinline__ float sigf(float x){ return 1.f/(1.f+expf(-x)); }

// ---------------- emission[b,t,k] = x_emb[b,t,:] . sm[k,:] ----------------
__global__ void k_emission(const float* __restrict__ xemb, const float* __restrict__ sm){
    int bt = blockIdx.x;                         // b*256+t
    __shared__ float xr[Hh];
    for (int i = threadIdx.x; i < Hh; i += 256) xr[i] = xemb[bt*Hh + i];
    __syncthreads();
    int w = threadIdx.x >> 5, l = threadIdx.x & 31;
    for (int k = w; k < Kk; k += 8){
        float s = 0.f;
        for (int i = l; i < Hh; i += 32) s += xr[i] * sm[k*Hh + i];
        #pragma unroll
        for (int o = 16; o; o >>= 1) s += __shfl_xor_sync(0xffffffffu, s, o);
        if (l == 0) d_emission[bt*Kk + k] = s;
    }
}

// ---------------- transition[j,k] = sm[j,:].sm[k,:]; also exp() ----------------
__global__ void k_trans(const float* __restrict__ sm){
    int jk = blockIdx.x; int j = jk / Kk, k = jk % Kk;
    int l = threadIdx.x;
    float s = 0.f;
    for (int i = l; i < Hh; i += 32) s += sm[j*Hh+i] * sm[k*Hh+i];
    #pragma unroll
    for (int o = 16; o; o >>= 1) s += __shfl_xor_sync(0xffffffffu, s, o);
    if (l == 0){ d_trans[jk] = s; d_transexp[jk] = expf(s); }
}

// ---------------- CRF forward (scaled-probability recursion) ----------------
// alpha_new[k] = M + log( sum_j exp(alpha_j - M) * exp(trans[j,k]) ) + em
__global__ void k_forward(){
    __shared__ float Es[Kk*Kk];
    for (int i = threadIdx.x; i < Kk*Kk; i += 256) Es[i] = d_transexp[i];
    __syncthreads();
    int w = threadIdx.x >> 5, l = threadIdx.x & 31;
    int b = w;
    bool act = (l < Kk);
    int kc = act ? l : 0;
    float a = act ? d_emission[(b*Tt + 0)*Kk + kc] : -INFINITY;
    if (act) d_alphas[(0*Bb + b)*Kk + kc] = a;
    float M = a;
    #pragma unroll
    for (int o = 16; o; o >>= 1) M = fmaxf(M, __shfl_xor_sync(0xffffffffu, M, o));
    float u = act ? expf(a - M) : 0.f;
    for (int t = 1; t < Tt; t++){
        float s = 0.f;
        #pragma unroll
        for (int j = 0; j < Kk; j++){
            float uj = __shfl_sync(0xffffffffu, u, j);
            s += uj * Es[j*Kk + kc];
        }
        if (act){
            float em = d_emission[(b*Tt + t)*Kk + kc];
            a = M + logf(s) + em;
            d_alphas[(t*Bb + b)*Kk + kc] = a;
        } else a = -INFINITY;
        float Mn = a;
        #pragma unroll
        for (int o = 16; o; o >>= 1) Mn = fmaxf(Mn, __shfl_xor_sync(0xffffffffu, Mn, o));
        u = act ? expf(a - Mn) : 0.f;
        M = Mn;
    }
}

// ---------------- CRF backward relaxed sampling ----------------
__global__ void k_backward(const float* __restrict__ gum){
    __shared__ float Ts[Kk*Kk];
    for (int i = threadIdx.x; i < Kk*Kk; i += 256) Ts[i] = d_trans[i];
    __syncthreads();
    int w = threadIdx.x >> 5, l = threadIdx.x & 31;
    int b = w;
    bool act = (l < Kk);
    int kc = act ? l : 0;
    int zn = 0;
    for (int step = 0; step <= NSTEP; step++){
        int t = Tt - 1 - step;
        float a;
        if (t == Tt - 1) a = act ? d_alphas[(t*Bb + b)*Kk + kc] : -INFINITY;
        else             a = act ? (d_alphas[(t*Bb + b)*Kk + kc] + Ts[kc*Kk + zn]) : -INFINITY;
        // log_softmax
        float M = a;
        #pragma unroll
        for (int o = 16; o; o >>= 1) M = fmaxf(M, __shfl_xor_sync(0xffffffffu, M, o));
        float e = act ? expf(a - M) : 0.f;
        float S = e;
        #pragma unroll
        for (int o = 16; o; o >>= 1) S += __shfl_xor_sync(0xffffffffu, S, o);
        float logit = a - (M + logf(S));
        float y = act ? (logit + gum[(t*Bb + b)*Kk + kc]) : -INFINITY;
        // argmax (first index on tie)
        float v = y; int idx = act ? kc : 1000;
        #pragma unroll
        for (int o = 16; o; o >>= 1){
            float vo = __shfl_xor_sync(0xffffffffu, v, o);
            int   io = __shfl_xor_sync(0xffffffffu, idx, o);
            if (vo > v || (vo == v && io < idx)){ v = vo; idx = io; }
        }
        zn = idx;
        // relaxed = softmax(y / tau)
        float ym = y;
        #pragma unroll
        for (int o = 16; o; o >>= 1) ym = fmaxf(ym, __shfl_xor_sync(0xffffffffu, ym, o));
        float ee = act ? expf((y - ym) / TAUf) : 0.f;
        float Se = ee;
        #pragma unroll
        for (int o = 16; o; o >>= 1) Se += __shfl_xor_sync(0xffffffffu, Se, o);
        if (act) d_relaxed[(t*Bb + b)*Kk + kc] = ee / Se;
        if (l == 0) d_z[t*Bb + b] = zn;
    }
}

// ---------------- dec_in[t,b,:] = relaxed[t,b,:]@sm + emb[x[b,t],:] ----------------
__global__ void k_decin(const float* __restrict__ sm, const float* __restrict__ emb,
                        const int* __restrict__ x){
    int tb = blockIdx.x;            // t*8+b, t in [0,255)
    int t = tb >> 3, b = tb & 7;
    __shared__ float r[Kk];
    if (threadIdx.x < Kk) r[threadIdx.x] = d_relaxed[(t*Bb + b)*Kk + threadIdx.x];
    __syncthreads();
    int xv = x[b*Tt + t];
    for (int h = threadIdx.x; h < Hh; h += 256){
        float acc = emb[(size_t)xv*Hh + h];
        #pragma unroll
        for (int k = 0; k < Kk; k++) acc += r[k] * sm[k*Hh + h];
        d_decin[tb*Hh + h] = acc;
    }
}

// ---------------- entropy of softmax(emission), masked mean ----------------
__global__ void k_entropy(const int* __restrict__ attn){
    int tid = threadIdx.x;
    float es = 0.f, ms = 0.f;
    for (int i = tid; i < Bb*Tt; i += 256){
        int b = i >> 8, t = i & 255;
        int base = (b*Tt + t)*Kk;
        float M = -INFINITY;
        for (int k = 0; k < Kk; k++) M = fmaxf(M, d_emission[base + k]);
        float S = 0.f;
        for (int k = 0; k < Kk; k++) S += expf(d_emission[base + k] - M);
        float lse = M + logf(S);
        float ent = 0.f;
        for (int k = 0; k < Kk; k++){
            float lp = d_emission[base + k] - lse;
            ent -= expf(lp) * lp;
        }
        float m = (float)attn[b*Tt + t];
        es += ent * m; ms += m;
    }
    __shared__ float r1[8], r2[8];
    int w = tid >> 5, l = tid & 31;
    #pragma unroll
    for (int o = 16; o; o >>= 1){ es += __shfl_xor_sync(0xffffffffu, es, o);
                                  ms += __shfl_xor_sync(0xffffffffu, ms, o); }
    if (l == 0){ r1[w] = es; r2[w] = ms; }
    __syncthreads();
    if (tid == 0){
        float a = 0, c = 0;
        for (int q = 0; q < 8; q++){ a += r1[q]; c += r2[q]; }
        d_entsum[0] = a; d_entsum[1] = c;
    }
}

// ---------------- reset barrier flags (per graph replay) ----------------
__global__ void k_zero(){ if (threadIdx.x < GL) d_flags[threadIdx.x] = 0; }

// ---------------- persistent LSTM: weights resident in SMEM ----------------
#define LSTM_SMEM ((2*4*NJ*Hh + 2*Bb*Hh + 4*NJ*Bb + NJ*Bb) * 4)

__global__ void __launch_bounds__(256, 1) k_lstm(const float* __restrict__ Wih,
                                                 const float* __restrict__ Whh,
                                                 const float* __restrict__ bl){
    extern __shared__ float smem[];
    float* ws  = smem;                    // [2][4*NJ][Hh]
    float* xs  = ws + 2*4*NJ*Hh;          // [Bb][Hh]
    float* hsm = xs + Bb*Hh;              // [Bb][Hh]
    float* gsm = hsm + Bb*Hh;             // [4*NJ][Bb]
    float* csm = gsm + 4*NJ*Bb;           // [NJ][Bb]
    int tid = threadIdx.x, bx = blockIdx.x;
    int jbase = bx * NJ;

    for (int i = tid; i < 4*NJ*Hh; i += 256){
        int row = i / Hh;                 // g*NJ+jj
        int g = row / NJ, jj = row % NJ, kcol = i % Hh;
        int grow = g*Hh + jbase + jj;
        ws[i]             = Wih[(size_t)grow*Hh + kcol];
        ws[4*NJ*Hh + i]   = Whh[(size_t)grow*Hh + kcol];
    }
    for (int i = tid; i < Bb*Hh; i += 256) hsm[i] = 0.f;
    if (tid < NJ*Bb) csm[tid] = 0.f;
    {   // preload x_0
        const float4* src = (const float4*)d_decin;
        float4* dst = (float4*)xs;
        for (int i = tid; i < Bb*Hh/4; i += 256) dst[i] = src[i];
    }
    __syncthreads();

    int w = tid >> 5, l = tid & 31;
    int pr0 = w * 3;                      // 3 (gate,jj) pairs per warp
    const float4* wi4[3]; const float4* wh4[3]; float bias[3];
    #pragma unroll
    for (int p = 0; p < 3; p++){
        int pr = pr0 + p;
        wi4[p] = (const float4*)&ws[pr*Hh];
        wh4[p] = (const float4*)&ws[(4*NJ + pr)*Hh];
        int g = pr / NJ, jj = pr % NJ;
        bias[p] = bl[g*Hh + jbase + jj];
    }

    for (int t = 0; t < NSTEP; t++){
        float acc[3][8];
        #pragma unroll
        for (int p = 0; p < 3; p++)
            #pragma unroll
            for (int b = 0; b < 8; b++) acc[p][b] = 0.f;

        const float4* xs4 = (const float4*)xs;
        const float4* hs4 = (const float4*)hsm;
        #pragma unroll
        for (int it = 0; it < 6; it++){
            int k4 = it*32 + l;
            float4 xv[8], hv[8];
            #pragma unroll
            for (int b = 0; b < 8; b++){ xv[b] = xs4[b*192 + k4]; hv[b] = hs4[b*192 + k4]; }
            #pragma unroll
            for (int p = 0; p < 3; p++){
                float4 wi = wi4[p][k4], wh = wh4[p][k4];
                #pragma unroll
                for (int b = 0; b < 8; b++){
                    acc[p][b] += wi.x*xv[b].x + wi.y*xv[b].y + wi.z*xv[b].z + wi.w*xv[b].w;
                    acc[p][b] += wh.x*hv[b].x + wh.y*hv[b].y + wh.z*hv[b].z + wh.w*hv[b].w;
                }
            }
        }
        #pragma unroll
        for (int p = 0; p < 3; p++)
            #pragma unroll
            for (int b = 0; b < 8; b++){
                float v = acc[p][b];
                #pragma unroll
                for (int o = 16; o; o >>= 1) v += __shfl_xor_sync(0xffffffffu, v, o);
                if (l == 0) gsm[(pr0 + p)*Bb + b] = v + bias[p];
            }
        __syncthreads();

        if (tid < NJ*Bb){
            int jj = tid >> 3, b = tid & 7;
            float gi = gsm[(0*NJ + jj)*Bb + b];
            float gf = gsm[(1*NJ + jj)*Bb + b];
            float gg = gsm[(2*NJ + jj)*Bb + b];
            float go = gsm[(3*NJ + jj)*Bb + b];
            float c  = csm[tid];
            float cn = sigf(gf)*c + sigf(gi)*tanhf(gg);
            float hn = sigf(go)*tanhf(cn);
            csm[tid] = cn;
            int j = jbase + jj;
            d_hbuf[(t & 1)*Bb*Hh + b*Hh + j] = hn;
            d_hs[(t*Bb + b)*Hh + j] = hn;
        }
        // ---- grid barrier (per-block flag slots) ----
        __syncthreads();
        if (tid == 0){ __threadfence(); d_flags[bx] = t + 1; }
        if (tid < 32){
            bool done = false;
            while (!done){
                done = true;
                for (int i = tid; i < GL; i += 32)
                    if (d_flags[i] < t + 1) done = false;
                done = __all_sync(0xffffffffu, done);
            }
            __threadfence();
        }
        __syncthreads();
        // ---- load next-step activations ----
        if (t < NSTEP - 1){
            const float4* src = (const float4*)&d_decin[(size_t)(t+1)*Bb*Hh];
            float4* dst = (float4*)xs;
            for (int i = tid; i < Bb*Hh/4; i += 256) dst[i] = src[i];
        }
        {
            const float4* hb = (const float4*)&d_hbuf[(t & 1)*Bb*Hh];
            float4* dst = (float4*)hsm;
            for (int i = tid; i < Bb*Hh/4; i += 256) dst[i] = __ldcg(&hb[i]);
        }
        __syncthreads();
    }
}

// ---------------- fused projection GEMM + exp-sum partials ----------------
__global__ void __launch_bounds__(256, 2) k_gemm(const float* __restrict__ Wout,
                                                 const float* __restrict__ bout){
    __shared__ __align__(16) float As[GBK][GTM];
    __shared__ __align__(16) float Bs[GBK][GTN];
    int tbb = blockIdx.x, vb = blockIdx.y;
    int tid = threadIdx.x;
    int tx = tid & 15, ty = tid >> 4;
    int tbBase = tbb*GTM, vBase = vb*GTN;
    float c[8][8];
    #pragma unroll
    for (int i = 0; i < 8; i++)
        #pragma unroll
        for (int j = 0; j < 8; j++) c[i][j] = 0.f;

    for (int kt = 0; kt < Hh; kt += GBK){
        #pragma unroll
        for (int q = 0; q < 2; q++){
            int idx = tid*2 + q;
            int row = idx >> 2, k4 = idx & 3;
            int gr = tbBase + row;
            float4 av = (gr < NTB) ? *(const float4*)&d_hs[(size_t)gr*Hh + kt + k4*4]
                                   : make_float4(0,0,0,0);
            As[k4*4+0][row] = av.x; As[k4*4+1][row] = av.y;
            As[k4*4+2][row] = av.z; As[k4*4+3][row] = av.w;
            int vr = vBase + row;
            float4 bv = (vr < Vv) ? *(const float4*)&Wout[(size_t)vr*Hh + kt + k4*4]
                                  : make_float4(0,0,0,0);
            Bs[k4*4+0][row] = bv.x; Bs[k4*4+1][row] = bv.y;
            Bs[k4*4+2][row] = bv.z; Bs[k4*4+3][row] = bv.w;
        }
        __syncthreads();
        #pragma unroll
        for (int kk = 0; kk < GBK; kk++){
            float a[8], b[8];
            *(float4*)&a[0] = *(float4*)&As[kk][ty*8];
            *(float4*)&a[4] = *(float4*)&As[kk][ty*8+4];
            *(float4*)&b[0] = *(float4*)&Bs[kk][tx*8];
            *(float4*)&b[4] = *(float4*)&Bs[kk][tx*8+4];
            #pragma unroll
            for (int i = 0; i < 8; i++)
                #pragma unroll
                for (int j = 0; j < 8; j++) c[i][j] += a[i]*b[j];
        }
        __syncthreads();
    }
    // epilogue: exp + row sums
    float bo[8];
    #pragma unroll
    for (int j = 0; j < 8; j++){
        int v = vBase + tx*8 + j;
        bo[j] = (v < Vv) ? bout[v] : 0.f;
    }
    float rowsum[8];
    #pragma unroll
    for (int i = 0; i < 8; i++){
        float s = 0.f;
        #pragma unroll
        for (int j = 0; j < 8; j++){
            int v = vBase + tx*8 + j;
            if (v < Vv) s += expf(c[i][j] + bo[j]);
        }
        rowsum[i] = s;
    }
    __syncthreads();
    float* red = &As[0][0];               // 128*16 floats fits in As
    #pragma unroll
    for (int i = 0; i < 8; i++) red[(ty*8 + i)*16 + tx] = rowsum[i];
    __syncthreads();
    if (tid < GTM){
        float s = 0.f;
        #pragma unroll
        for (int q = 0; q < 16; q++) s += red[tid*16 + q];
        d_partial[(size_t)(tbBase + tid)*NVB + vb] = s;
    }
}

// ---------------- target-token logits ----------------
__global__ void k_tgt(const float* __restrict__ Wout, const float* __restrict__ bout,
                      const int* __restrict__ x){
    int tb = blockIdx.x;                 // t*8+b
    int t = tb >> 3, b = tb & 7;
    int tgt = x[b*Tt + t + 1];
    int tid = threadIdx.x;
    float s = 0.f;
    for (int h = tid; h < Hh; h += 256) s += d_hs[(size_t)tb*Hh + h] * Wout[(size_t)tgt*Hh + h];
    __shared__ float r8[8];
    int w = tid >> 5, l = tid & 31;
    #pragma unroll
    for (int o = 16; o; o >>= 1) s += __shfl_xor_sync(0xffffffffu, s, o);
    if (l == 0) r8[w] = s;
    __syncthreads();
    if (tid == 0){
        float tot = 0.f;
        for (int q = 0; q < 8; q++) tot += r8[q];
        d_tgtlogit[tb] = tot + bout[tgt];
    }
}

// ---------------- final loss + outputs ----------------
__global__ void k_final(const int* __restrict__ attn, float* __restrict__ out, int out_size){
    int tid = threadIdx.x;
    float accs = 0.f, accm = 0.f;
    for (int tb = tid; tb < NTB; tb += 256){
        float s = 0.f;
        for (int q = 0; q < NVB; q++) s += d_partial[(size_t)tb*NVB + q];
        float lse = logf(s);
        int t = tb >> 3, b = tb & 7;
        float m = (float)attn[b*Tt + t + 1];
        accs += (d_tgtlogit[tb] - lse) * m;
        accm += m;
    }
    __shared__ float r1[8], r2[8];
    int w = tid >> 5, l = tid & 31;
    #pragma unroll
    for (int o = 16; o; o >>= 1){ accs += __shfl_xor_sync(0xffffffffu, accs, o);
                                  accm += __shfl_xor_sync(0xffffffffu, accm, o); }
    if (l == 0){ r1[w] = accs; r2[w] = accm; }
    __syncthreads();
    if (tid == 0){
        float a = 0, cnt = 0;
        for (int q = 0; q < 8; q++){ a += r1[q]; cnt += r2[q]; }
        float plp = a / cnt;
        float ent = d_entsum[0] / d_entsum[1];
        out[0] = -(plp + ZBETA * ent);
    }
    // z_sample (as float), row-major [B,T]
    for (int i = tid; i < Bb*Tt; i += 256){
        if (1 + i < out_size){
            int b = i / Tt, t = i % Tt;
            out[1 + i] = (float)d_z[t*Bb + b];
        }
    }
    for (int i = 1 + Bb*Tt + tid; i < out_size; i += 256) out[i] = 0.f;
}

// ---------------- launch ----------------
extern "C" void kernel_launch(void* const* d_in, const int* in_sizes, int n_in,
                              void* d_out, int out_size){
    const float* xemb = (const float*)d_in[0];
    const float* sm   = (const float*)d_in[1];
    const float* emb  = (const float*)d_in[2];
    const float* Wih  = (const float*)d_in[3];
    const float* Whh  = (const float*)d_in[4];
    const float* bl   = (const float*)d_in[5];
    const float* Wout = (const float*)d_in[6];
    const float* bout = (const float*)d_in[7];
    const float* gum  = (const float*)d_in[8];
    const int*   x    = (const int*)d_in[9];
    const int*   attn = (const int*)d_in[10];
    float* out = (float*)d_out;

    cudaFuncSetAttribute(k_lstm, cudaFuncAttributeMaxDynamicSharedMemorySize, LSTM_SMEM);

    k_emission<<<Bb*Tt, 256>>>(xemb, sm);
    k_trans<<<Kk*Kk, 32>>>(sm);
    k_forward<<<1, 256>>>();
    k_backward<<<1, 256>>>(gum);
    k_decin<<<NSTEP*Bb, 256>>>(sm, emb, x);
    k_entropy<<<1, 256>>>(attn);
    k_zero<<<1, 128>>>();
    k_lstm<<<GL, 256, LSTM_SMEM>>>(Wih, Whh, bl);
    dim3 gg(NTB/GTM + ((NTB%GTM)?1:0), NVB);
    k_gemm<<<gg, 256>>>(Wout, bout);
    k_tgt<<<NTB, 256>>>(Wout, bout, x);
    k_final<<<1, 256>>>(attn, out, out_size);
}

// round 5
// speedup vs baseline: 1.6040x; 1.6040x over previous
#include <cuda_runtime.h>
#include <cuda_bf16.h>
#include <math.h>

#define Bb 8
#define Tt 256
#define Kk 20
#define Hh 768
#define Vv 30522
#define NSTEP 255            // T-1 LSTM steps
#define NTB (NSTEP*Bb)       // 2040 decoder tokens
#define TAUf 1.0f
#define ZBETA 1.0f

#define GTN 128
#define NVB ((Vv + GTN - 1) / GTN)   // 239 v-blocks (239*128 = 30592)
#define MPAD 2048
#define VPAD (NVB*GTN)

#define GL 128               // LSTM persistent blocks
#define NJ 6                 // hidden units per block (128*6 = 768)

// ---------------- device scratch (static, no allocations) ----------------
__device__ __align__(256) float d_trans[Kk*Kk];
__device__ __align__(256) float d_transexp[Kk*Kk];
__device__ __align__(256) float d_emission[Bb*Tt*Kk];     // [b][t][k]
__device__ __align__(256) float d_alphas[Tt*Bb*Kk];       // [t][b][k]
__device__ __align__(256) unsigned char d_cand_arg[Tt*Bb*Kk];
__device__ __align__(256) float d_cand_rel[Tt*Bb*Kk*Kk];  // [t][b][zn][k]
__device__ __align__(256) int   d_z[Tt*Bb];               // [t][b]
__device__ __align__(256) int   d_sel[NSTEP*Bb];          // chosen zn per (t,b)
__device__ __align__(256) float d_decin[NSTEP*Bb*Hh];     // [t][b][h]
__device__ __align__(256) float d_hs[NSTEP*Bb*Hh];        // [t][b][h]
__device__ __align__(256) unsigned short d_hsb[MPAD*Hh];  // bf16 hs (padded rows)
__device__ __align__(256) unsigned short d_woutb[(size_t)VPAD*Hh]; // bf16 Wout
__device__ __align__(256) float d_hbuf[2*Bb*Hh];
__device__ __align__(256) float d_partial[MPAD*NVB];
__device__ __align__(256) float d_lse[NTB];
__device__ __align__(256) float d_tgtlogit[NTB];
__device__ __align__(256) float d_entsum[2];
__device__ volatile int d_flags[GL];

__device__ __forceinline__ float sigf(float x){ return 1.f/(1.f+expf(-x)); }

// FMA-only exp (rel err ~2.4e-6), keeps MUFU free. Valid for |x| < ~80.
__device__ __forceinline__ float fexp(float x){
    float y = x * 1.4426950408889634f;
    int e = __float2int_rn(y);
    float f = y - (float)e;
    float p = 1.3333558146428443e-3f;
    p = fmaf(p, f, 9.6181291976021928e-3f);
    p = fmaf(p, f, 5.5504108664821580e-2f);
    p = fmaf(p, f, 2.4022650695910071e-1f);
    p = fmaf(p, f, 6.9314718055994531e-1f);
    p = fmaf(p, f, 1.0f);
    return p * __int_as_float((e + 127) << 23);
}

// ---------------- emission[b,t,k] = x_emb[b,t,:] . sm[k,:] ----------------
__global__ void k_emission(const float* __restrict__ xemb, const float* __restrict__ sm){
    int bt = blockIdx.x;                         // b*256+t
    __shared__ float xr[Hh];
    for (int i = threadIdx.x; i < Hh; i += 256) xr[i] = xemb[bt*Hh + i];
    __syncthreads();
    int w = threadIdx.x >> 5, l = threadIdx.x & 31;
    for (int k = w; k < Kk; k += 8){
        float s = 0.f;
        for (int i = l; i < Hh; i += 32) s += xr[i] * sm[k*Hh + i];
        #pragma unroll
        for (int o = 16; o; o >>= 1) s += __shfl_xor_sync(0xffffffffu, s, o);
        if (l == 0) d_emission[bt*Kk + k] = s;
    }
}

// ---------------- transition[j,k] = sm[j,:].sm[k,:]; also exp() ----------------
__global__ void k_trans(const float* __restrict__ sm){
    int jk = blockIdx.x; int j = jk / Kk, k = jk % Kk;
    int l = threadIdx.x;
    float s = 0.f;
    for (int i = l; i < Hh; i += 32) s += sm[j*Hh+i] * sm[k*Hh+i];
    #pragma unroll
    for (int o = 16; o; o >>= 1) s += __shfl_xor_sync(0xffffffffu, s, o);
    if (l == 0){ d_trans[jk] = s; d_transexp[jk] = expf(s); }
}

// ---------------- CRF forward (R1 log-domain recursion, verbatim) ----------------
// alpha_new[k] = M + log( sum_j exp(alpha_j - M) * exp(trans[j,k]) ) + em
__global__ void k_forward(){
    __shared__ float Es[Kk*Kk];
    for (int i = threadIdx.x; i < Kk*Kk; i += 256) Es[i] = d_transexp[i];
    __syncthreads();
    int w = threadIdx.x >> 5, l = threadIdx.x & 31;
    int b = w;
    bool act = (l < Kk);
    int kc = act ? l : 0;
    float a = act ? d_emission[(b*Tt + 0)*Kk + kc] : -INFINITY;
    if (act) d_alphas[(0*Bb + b)*Kk + kc] = a;
    float M = a;
    #pragma unroll
    for (int o = 16; o; o >>= 1) M = fmaxf(M, __shfl_xor_sync(0xffffffffu, M, o));
    float u = act ? expf(a - M) : 0.f;
    for (int t = 1; t < Tt; t++){
        float s = 0.f;
        #pragma unroll
        for (int j = 0; j < Kk; j++){
            float uj = __shfl_sync(0xffffffffu, u, j);
            s += uj * Es[j*Kk + kc];
        }
        if (act){
            float em = d_emission[(b*Tt + t)*Kk + kc];
            a = M + logf(s) + em;
            d_alphas[(t*Bb + b)*Kk + kc] = a;
        } else a = -INFINITY;
        float Mn = a;
        #pragma unroll
        for (int o = 16; o; o >>= 1) Mn = fmaxf(Mn, __shfl_xor_sync(0xffffffffu, Mn, o));
        u = act ? expf(a - Mn) : 0.f;
        M = Mn;
    }
}

// ---------------- candidate backward-sampling: all (t,b,zn) in parallel -----------
__global__ void k_cand(const float* __restrict__ gum){
    __shared__ float Ts[Kk*Kk];
    for (int i = threadIdx.x; i < Kk*Kk; i += 256) Ts[i] = d_trans[i];
    __syncthreads();
    int t = blockIdx.x >> 3, b = blockIdx.x & 7;
    int w = threadIdx.x >> 5, l = threadIdx.x & 31;
    bool act = (l < Kk);
    int kc = act ? l : 0;
    float al = act ? d_alphas[(t*Bb + b)*Kk + kc] : -INFINITY;
    float gl = act ? gum[(t*Bb + b)*Kk + kc] : 0.f;
    bool last = (t == Tt - 1);
    int znHi = last ? 1 : Kk;
    for (int zn = w; zn < znHi; zn += 8){
        float a = last ? al : (act ? (al + Ts[kc*Kk + zn]) : -INFINITY);
        // log_softmax (mirrors reference rounding path)
        float M = a;
        #pragma unroll
        for (int o = 16; o; o >>= 1) M = fmaxf(M, __shfl_xor_sync(0xffffffffu, M, o));
        float e = act ? expf(a - M) : 0.f;
        float S = e;
        #pragma unroll
        for (int o = 16; o; o >>= 1) S += __shfl_xor_sync(0xffffffffu, S, o);
        float logit = a - (M + logf(S));
        float y = act ? (logit + gl) : -INFINITY;
        // argmax (first index on tie)
        float v = y; int idx = act ? kc : 1000;
        #pragma unroll
        for (int o = 16; o; o >>= 1){
            float vo = __shfl_xor_sync(0xffffffffu, v, o);
            int   io = __shfl_xor_sync(0xffffffffu, idx, o);
            if (vo > v || (vo == v && io < idx)){ v = vo; idx = io; }
        }
        // relaxed = softmax(y / tau)
        float ym = y;
        #pragma unroll
        for (int o = 16; o; o >>= 1) ym = fmaxf(ym, __shfl_xor_sync(0xffffffffu, ym, o));
        float ee = act ? expf((y - ym) / TAUf) : 0.f;
        float Se = ee;
        #pragma unroll
        for (int o = 16; o; o >>= 1) Se += __shfl_xor_sync(0xffffffffu, Se, o);
        if (act) d_cand_rel[((size_t)(t*Bb + b)*Kk + zn)*Kk + kc] = ee / Se;
        if (l == 0) d_cand_arg[(t*Bb + b)*Kk + zn] = (unsigned char)idx;
    }
}

// ---------------- tiny pointer-chase over candidate argmaxes (SMEM) ----------------
__global__ void k_chase(){
    __shared__ unsigned char sarr[Tt*Bb*Kk];     // 40960 B
    const uint4* src = (const uint4*)d_cand_arg;
    uint4* dst = (uint4*)sarr;
    for (int i = threadIdx.x; i < Tt*Bb*Kk/16; i += 256) dst[i] = src[i];
    __syncthreads();
    if (threadIdx.x < Bb){
        int b = threadIdx.x;
        int z = sarr[((Tt-1)*Bb + b)*Kk + 0];
        d_z[(Tt-1)*Bb + b] = z;
        for (int t = Tt - 2; t >= 0; t--){
            int zn = z;
            d_sel[t*Bb + b] = zn;
            z = sarr[(t*Bb + b)*Kk + zn];
            d_z[t*Bb + b] = z;
        }
    }
}

// ---------------- dec_in[t,b,:] = relaxed[t,b,:]@sm + emb[x[b,t],:] ----------------
__global__ void k_decin(const float* __restrict__ sm, const float* __restrict__ emb,
                        const int* __restrict__ x){
    int tb = blockIdx.x;            // t*8+b, t in [0,255)
    int t = tb >> 3, b = tb & 7;
    int sel = d_sel[tb];
    __shared__ float r[Kk];
    if (threadIdx.x < Kk) r[threadIdx.x] = d_cand_rel[((size_t)(t*Bb + b)*Kk + sel)*Kk + threadIdx.x];
    __syncthreads();
    int xv = x[b*Tt + t];
    for (int h = threadIdx.x; h < Hh; h += 256){
        float acc = emb[(size_t)xv*Hh + h];
        #pragma unroll
        for (int k = 0; k < Kk; k++) acc += r[k] * sm[k*Hh + h];
        d_decin[tb*Hh + h] = acc;
    }
}

// ---------------- entropy of softmax(emission), masked mean ----------------
__global__ void k_entropy(const int* __restrict__ attn){
    int tid = threadIdx.x;
    float es = 0.f, ms = 0.f;
    for (int i = tid; i < Bb*Tt; i += 256){
        int base = i*Kk;
        float M = -INFINITY;
        for (int k = 0; k < Kk; k++) M = fmaxf(M, d_emission[base + k]);
        float S = 0.f;
        for (int k = 0; k < Kk; k++) S += expf(d_emission[base + k] - M);
        float lse = M + logf(S);
        float ent = 0.f;
        for (int k = 0; k < Kk; k++){
            float lp = d_emission[base + k] - lse;
            ent -= expf(lp) * lp;
        }
        float m = (float)attn[i];
        es += ent * m; ms += m;
    }
    __shared__ float r1[8], r2[8];
    int w = tid >> 5, l = tid & 31;
    #pragma unroll
    for (int o = 16; o; o >>= 1){ es += __shfl_xor_sync(0xffffffffu, es, o);
                                  ms += __shfl_xor_sync(0xffffffffu, ms, o); }
    if (l == 0){ r1[w] = es; r2[w] = ms; }
    __syncthreads();
    if (tid == 0){
        float a = 0, c = 0;
        for (int q = 0; q < 8; q++){ a += r1[q]; c += r2[q]; }
        d_entsum[0] = a; d_entsum[1] = c;
    }
}

// ---------------- reset barrier flags ----------------
__global__ void k_zero(){ if (threadIdx.x < GL) d_flags[threadIdx.x] = 0; }

// ---------------- persistent LSTM ----------------
#define LSTM_SMEM ((2*4*NJ*Hh + 2*Bb*Hh + 4*NJ*Bb + NJ*Bb) * 4)

__global__ void __launch_bounds__(256, 1) k_lstm(const float* __restrict__ Wih,
                                                 const float* __restrict__ Whh,
                                                 const float* __restrict__ bl){
    extern __shared__ float smem[];
    float* ws  = smem;
    float* xs  = ws + 2*4*NJ*Hh;
    float* hsm = xs + Bb*Hh;
    float* gsm = hsm + Bb*Hh;
    float* csm = gsm + 4*NJ*Bb;
    int tid = threadIdx.x, bx = blockIdx.x;
    int jbase = bx * NJ;

    for (int i = tid; i < 4*NJ*Hh; i += 256){
        int row = i / Hh;
        int g = row / NJ, jj = row % NJ, kcol = i % Hh;
        int grow = g*Hh + jbase + jj;
        ws[i]             = Wih[(size_t)grow*Hh + kcol];
        ws[4*NJ*Hh + i]   = Whh[(size_t)grow*Hh + kcol];
    }
    for (int i = tid; i < Bb*Hh; i += 256) hsm[i] = 0.f;
    if (tid < NJ*Bb) csm[tid] = 0.f;
    {
        const float4* src = (const float4*)d_decin;
        float4* dst = (float4*)xs;
        for (int i = tid; i < Bb*Hh/4; i += 256) dst[i] = src[i];
    }
    __syncthreads();

    int w = tid >> 5, l = tid & 31;
    int pr0 = w * 3;
    const float4* wi4[3]; const float4* wh4[3]; float bias[3];
    #pragma unroll
    for (int p = 0; p < 3; p++){
        int pr = pr0 + p;
        wi4[p] = (const float4*)&ws[pr*Hh];
        wh4[p] = (const float4*)&ws[(4*NJ + pr)*Hh];
        int g = pr / NJ, jj = pr % NJ;
        bias[p] = bl[g*Hh + jbase + jj];
    }

    for (int t = 0; t < NSTEP; t++){
        float acc[3][8];
        #pragma unroll
        for (int p = 0; p < 3; p++)
            #pragma unroll
            for (int b = 0; b < 8; b++) acc[p][b] = 0.f;

        const float4* xs4 = (const float4*)xs;
        const float4* hs4 = (const float4*)hsm;
        #pragma unroll
        for (int it = 0; it < 6; it++){
            int k4 = it*32 + l;
            float4 xv[8], hv[8];
            #pragma unroll
            for (int b = 0; b < 8; b++){ xv[b] = xs4[b*192 + k4]; hv[b] = hs4[b*192 + k4]; }
            #pragma unroll
            for (int p = 0; p < 3; p++){
                float4 wi = wi4[p][k4], wh = wh4[p][k4];
                #pragma unroll
                for (int b = 0; b < 8; b++){
                    acc[p][b] += wi.x*xv[b].x + wi.y*xv[b].y + wi.z*xv[b].z + wi.w*xv[b].w;
                    acc[p][b] += wh.x*hv[b].x + wh.y*hv[b].y + wh.z*hv[b].z + wh.w*hv[b].w;
                }
            }
        }
        #pragma unroll
        for (int p = 0; p < 3; p++)
            #pragma unroll
            for (int b = 0; b < 8; b++){
                float v = acc[p][b];
                #pragma unroll
                for (int o = 16; o; o >>= 1) v += __shfl_xor_sync(0xffffffffu, v, o);
                if (l == 0) gsm[(pr0 + p)*Bb + b] = v + bias[p];
            }
        __syncthreads();

        if (tid < NJ*Bb){
            int jj = tid >> 3, b = tid & 7;
            float gi = gsm[(0*NJ + jj)*Bb + b];
            float gf = gsm[(1*NJ + jj)*Bb + b];
            float gg = gsm[(2*NJ + jj)*Bb + b];
            float go = gsm[(3*NJ + jj)*Bb + b];
            float c  = csm[tid];
            float cn = sigf(gf)*c + sigf(gi)*tanhf(gg);
            float hn = sigf(go)*tanhf(cn);
            csm[tid] = cn;
            int j = jbase + jj;
            d_hbuf[(t & 1)*Bb*Hh + b*Hh + j] = hn;
            d_hs[(t*Bb + b)*Hh + j] = hn;
        }
        __syncthreads();
        if (tid == 0){ __threadfence(); d_flags[bx] = t + 1; }
        if (tid < 32){
            bool done = false;
            while (!done){
                done = true;
                for (int i = tid; i < GL; i += 32)
                    if (d_flags[i] < t + 1) done = false;
                done = __all_sync(0xffffffffu, done);
            }
            __threadfence();
        }
        __syncthreads();
        if (t < NSTEP - 1){
            const float4* src = (const float4*)&d_decin[(size_t)(t+1)*Bb*Hh];
            float4* dst = (float4*)xs;
            for (int i = tid; i < Bb*Hh/4; i += 256) dst[i] = src[i];
        }
        {
            const float4* hb = (const float4*)&d_hbuf[(t & 1)*Bb*Hh];
            float4* dst = (float4*)hsm;
            for (int i = tid; i < Bb*Hh/4; i += 256) dst[i] = __ldcg(&hb[i]);
        }
        __syncthreads();
    }
}

// ---------------- fp32 -> bf16 conversions ----------------
__global__ void k_w2bf(const float* __restrict__ W){
    size_t i = ((size_t)blockIdx.x*256 + threadIdx.x) * 4;
    int row = (int)(i / Hh);
    float4 v = (row < Vv) ? *(const float4*)(W + i) : make_float4(0,0,0,0);
    __nv_bfloat162 p0 = __floats2bfloat162_rn(v.x, v.y);
    __nv_bfloat162 p1 = __floats2bfloat162_rn(v.z, v.w);
    uint2 o; o.x = *(unsigned*)&p0; o.y = *(unsigned*)&p1;
    *(uint2*)&d_woutb[i] = o;
}
__global__ void k_h2bf(){
    size_t i = ((size_t)blockIdx.x*256 + threadIdx.x) * 4;
    int row = (int)(i / Hh);
    float4 v = (row < NTB) ? *(const float4*)(d_hs + i) : make_float4(0,0,0,0);
    __nv_bfloat162 p0 = __floats2bfloat162_rn(v.x, v.y);
    __nv_bfloat162 p1 = __floats2bfloat162_rn(v.z, v.w);
    uint2 o; o.x = *(unsigned*)&p0; o.y = *(unsigned*)&p1;
    *(uint2*)&d_hsb[i] = o;
}

// ---------------- tensor-core GEMM (bf16 mma.sync) + exp-sum epilogue ----------------
__device__ __forceinline__ void cpa16(unsigned dst, const void* src){
    asm volatile("cp.async.cg.shared.global [%0], [%1], 16;\n" :: "r"(dst), "l"(src));
}
__device__ __forceinline__ void ldm4(unsigned addr, unsigned &r0, unsigned &r1,
                                     unsigned &r2, unsigned &r3){
    asm volatile("ldmatrix.sync.aligned.m8n8.x4.shared.b16 {%0,%1,%2,%3},[%4];"
                 : "=r"(r0), "=r"(r1), "=r"(r2), "=r"(r3) : "r"(addr));
}
__device__ __forceinline__ void mma16816(float* c, const unsigned* a, const unsigned* b){
    asm volatile("mma.sync.aligned.m16n8k16.row.col.f32.bf16.bf16.f32 "
                 "{%0,%1,%2,%3},{%4,%5,%6,%7},{%8,%9},{%0,%1,%2,%3};"
                 : "+f"(c[0]), "+f"(c[1]), "+f"(c[2]), "+f"(c[3])
                 : "r"(a[0]), "r"(a[1]), "r"(a[2]), "r"(a[3]), "r"(b[0]), "r"(b[1]));
}

__global__ void __launch_bounds__(256) k_gemm(const float* __restrict__ bout){
    extern __shared__ __align__(16) unsigned char smraw[];
    unsigned short* As = (unsigned short*)smraw;       // [2][128*64] bf16
    unsigned short* Bs = As + 2*128*64;                // [2][128*64] bf16
    float* red = (float*)smraw;                        // epilogue reuse (8KB)

    int tid = threadIdx.x;
    int wid = tid >> 5, lane = tid & 31;
    int wm = wid & 1, wn = wid >> 1;
    int jm = lane >> 3, rr = lane & 7;
    int g = lane >> 2, tg = lane & 3;
    int tbBase = blockIdx.x * 128, vBase = blockIdx.y * 128;

    const unsigned short* gA = d_hsb + (size_t)tbBase*Hh;
    const unsigned short* gB = d_woutb + (size_t)vBase*Hh;
    unsigned sA0 = (unsigned)__cvta_generic_to_shared(As);
    unsigned sB0 = (unsigned)__cvta_generic_to_shared(Bs);

    int crow = tid >> 3, cch = tid & 7;                // copy assignment base

    float c[4][4][4];
    #pragma unroll
    for (int mf = 0; mf < 4; mf++)
        #pragma unroll
        for (int nf = 0; nf < 4; nf++)
            #pragma unroll
            for (int q = 0; q < 4; q++) c[mf][nf][q] = 0.f;

    #define ISSUE(kt, stg) do{                                                        \
        unsigned bA = sA0 + (stg)*16384, bB = sB0 + (stg)*16384;                      \
        _Pragma("unroll")                                                             \
        for (int q = 0; q < 4; q++){                                                  \
            int row = crow + q*32, ch = cch;                                          \
            unsigned sw = (unsigned)(row*128 + ((ch ^ (row & 7)) << 4));              \
            cpa16(bA + sw, gA + (size_t)row*Hh + (kt)*64 + ch*8);                     \
            cpa16(bB + sw, gB + (size_t)row*Hh + (kt)*64 + ch*8);                     \
        }                                                                             \
        asm volatile("cp.async.commit_group;\n");                                     \
    } while(0)

    ISSUE(0, 0);
    for (int kt = 0; kt < 12; kt++){
        if (kt + 1 < 12) ISSUE(kt + 1, (kt + 1) & 1);
        if (kt + 1 < 12) asm volatile("cp.async.wait_group 1;\n");
        else             asm volatile("cp.async.wait_group 0;\n");
        __syncthreads();
        unsigned bA = sA0 + (kt & 1)*16384, bB = sB0 + (kt & 1)*16384;
        #pragma unroll
        for (int kf = 0; kf < 4; kf++){
            unsigned a[4][4];
            #pragma unroll
            for (int mf = 0; mf < 4; mf++){
                int row = wm*64 + mf*16 + ((jm & 1) << 3) + rr;
                unsigned off = (unsigned)(row*128 + kf*32 + ((jm >> 1) << 4));
                ldm4(bA + (off ^ ((unsigned)(row & 7) << 4)),
                     a[mf][0], a[mf][1], a[mf][2], a[mf][3]);
            }
            unsigned b[4][2];
            #pragma unroll
            for (int p = 0; p < 2; p++){
                int row = wn*32 + p*16 + ((jm >> 1) << 3) + rr;
                unsigned off = (unsigned)(row*128 + kf*32 + ((jm & 1) << 4));
                unsigned r0, r1, r2, r3;
                ldm4(bB + (off ^ ((unsigned)(row & 7) << 4)), r0, r1, r2, r3);
                b[2*p][0] = r0; b[2*p][1] = r1; b[2*p+1][0] = r2; b[2*p+1][1] = r3;
            }
            #pragma unroll
            for (int mf = 0; mf < 4; mf++)
                #pragma unroll
                for (int nf = 0; nf < 4; nf++)
                    mma16816(c[mf][nf], a[mf], b[nf]);
        }
        __syncthreads();
    }

    // epilogue: exp(logit + bias) row sums
    float rs[4][2];
    #pragma unroll
    for (int mf = 0; mf < 4; mf++){ rs[mf][0] = 0.f; rs[mf][1] = 0.f; }
    #pragma unroll
    for (int nf = 0; nf < 4; nf++){
        #pragma unroll
        for (int h = 0; h < 2; h++){
            int v = vBase + wn*32 + nf*8 + 2*tg + h;
            if (v < Vv){
                float bo = bout[v];
                #pragma unroll
                for (int mf = 0; mf < 4; mf++){
                    rs[mf][0] += fexp(c[mf][nf][h]     + bo);
                    rs[mf][1] += fexp(c[mf][nf][2 + h] + bo);
                }
            }
        }
    }
    __syncthreads();
    #pragma unroll
    for (int mf = 0; mf < 4; mf++)
        #pragma unroll
        for (int rh = 0; rh < 2; rh++)
            red[(wm*64 + mf*16 + rh*8 + g)*16 + wn*4 + tg] = rs[mf][rh];
    __syncthreads();
    if (tid < 128){
        float s = 0.f;
        #pragma unroll
        for (int q = 0; q < 16; q++) s += red[tid*16 + q];
        int tb = tbBase + tid;
        if (tb < NTB) d_partial[(size_t)tb*NVB + blockIdx.y] = s;
    }
}

// ---------------- target-token logits (fp32, exact) ----------------
__global__ void k_tgt(const float* __restrict__ Wout, const float* __restrict__ bout,
                      const int* __restrict__ x){
    int tb = blockIdx.x;
    int t = tb >> 3, b = tb & 7;
    int tgt = x[b*Tt + t + 1];
    int tid = threadIdx.x;
    float s = 0.f;
    for (int h = tid; h < Hh; h += 256) s += d_hs[(size_t)tb*Hh + h] * Wout[(size_t)tgt*Hh + h];
    __shared__ float r8[8];
    int w = tid >> 5, l = tid & 31;
    #pragma unroll
    for (int o = 16; o; o >>= 1) s += __shfl_xor_sync(0xffffffffu, s, o);
    if (l == 0) r8[w] = s;
    __syncthreads();
    if (tid == 0){
        float tot = 0.f;
        for (int q = 0; q < 8; q++) tot += r8[q];
        d_tgtlogit[tb] = tot + bout[tgt];
    }
}

// ---------------- parallel lse over v-block partials ----------------
__global__ void k_lse(){
    int w = threadIdx.x >> 5, l = threadIdx.x & 31;
    int tb = blockIdx.x*8 + w;               // 255*8 = 2040
    float s = 0.f;
    for (int q = l; q < NVB; q += 32) s += d_partial[(size_t)tb*NVB + q];
    #pragma unroll
    for (int o = 16; o; o >>= 1) s += __shfl_xor_sync(0xffffffffu, s, o);
    if (l == 0) d_lse[tb] = logf(s);
}

// ---------------- final loss + outputs ----------------
__global__ void k_final(const int* __restrict__ attn, float* __restrict__ out, int out_size){
    int tid = threadIdx.x;
    float accs = 0.f, accm = 0.f;
    for (int tb = tid; tb < NTB; tb += 256){
        int t = tb >> 3, b = tb & 7;
        float m = (float)attn[b*Tt + t + 1];
        accs += (d_tgtlogit[tb] - d_lse[tb]) * m;
        accm += m;
    }
    __shared__ float r1[8], r2[8];
    int w = tid >> 5, l = tid & 31;
    #pragma unroll
    for (int o = 16; o; o >>= 1){ accs += __shfl_xor_sync(0xffffffffu, accs, o);
                                  accm += __shfl_xor_sync(0xffffffffu, accm, o); }
    if (l == 0){ r1[w] = accs; r2[w] = accm; }
    __syncthreads();
    if (tid == 0){
        float a = 0, cnt = 0;
        for (int q = 0; q < 8; q++){ a += r1[q]; cnt += r2[q]; }
        float plp = a / cnt;
        float ent = d_entsum[0] / d_entsum[1];
        out[0] = -(plp + ZBETA * ent);
    }
    for (int i = tid; i < Bb*Tt; i += 256){
        if (1 + i < out_size){
            int b = i / Tt, t = i % Tt;
            out[1 + i] = (float)d_z[t*Bb + b];
        }
    }
    for (int i = 1 + Bb*Tt + tid; i < out_size; i += 256) out[i] = 0.f;
}

// ---------------- launch ----------------
extern "C" void kernel_launch(void* const* d_in, const int* in_sizes, int n_in,
                              void* d_out, int out_size){
    const float* xemb = (const float*)d_in[0];
    const float* sm   = (const float*)d_in[1];
    const float* emb  = (const float*)d_in[2];
    const float* Wih  = (const float*)d_in[3];
    const float* Whh  = (const float*)d_in[4];
    const float* bl   = (const float*)d_in[5];
    const float* Wout = (const float*)d_in[6];
    const float* bout = (const float*)d_in[7];
    const float* gum  = (const float*)d_in[8];
    const int*   x    = (const int*)d_in[9];
    const int*   attn = (const int*)d_in[10];
    float* out = (float*)d_out;

    cudaFuncSetAttribute(k_lstm, cudaFuncAttributeMaxDynamicSharedMemorySize, LSTM_SMEM);
    cudaFuncSetAttribute(k_gemm, cudaFuncAttributeMaxDynamicSharedMemorySize, 65536);

    k_zero<<<1, 128>>>();
    k_emission<<<Bb*Tt, 256>>>(xemb, sm);
    k_trans<<<Kk*Kk, 32>>>(sm);
    k_w2bf<<<(int)((size_t)VPAD*Hh/4/256), 256>>>(Wout);
    k_forward<<<1, 256>>>();
    k_cand<<<Tt*Bb, 256>>>(gum);
    k_chase<<<1, 256>>>();
    k_decin<<<NSTEP*Bb, 256>>>(sm, emb, x);
    k_entropy<<<1, 256>>>(attn);
    k_lstm<<<GL, 256, LSTM_SMEM>>>(Wih, Whh, bl);
    k_h2bf<<<(int)((size_t)MPAD*Hh/4/256), 256>>>();
    dim3 gg(MPAD/128, NVB);
    k_gemm<<<gg, 256, 65536>>>(bout);
    k_tgt<<<NTB, 256>>>(Wout, bout, x);
    k_lse<<<NTB/8, 256>>>();
    k_final<<<1, 256>>>(attn, out, out_size);
}